// round 9
// baseline (speedup 1.0000x reference)
#include <cuda_runtime.h>
#include <cuda_bf16.h>
#include <cstdint>

#define BQ 64
#define MB 256
#define DLL 524288LL
#define KT 32
#define NTT 16384
#define NCTA 152
#define SDIM 2048

// split-K scratch: chunk [0,NCTA) tensor side, [NCTA,2*NCTA) ffma side
__device__ float g_psim[2 * NCTA * BQ * MB];
__device__ float g_pnorm[2 * NCTA * MB];

// smem: tensor double buffer (2x40960) + ffma bank double buffer (2x8192)
#define A_HI 0u
#define A_LO 4096u
#define B_HI 8192u
#define B_LO 24576u
#define BUFB 40960u
#define FF_BANK 81920u
#define SMEM_TOTAL 98304u

static __device__ __forceinline__ uint32_t smem_u32(const void* p) {
    uint32_t a;
    asm("{ .reg .u64 t; cvta.to.shared.u64 t, %1; cvt.u32.u64 %0, t; }"
        : "=r"(a) : "l"(p));
    return a;
}
static __device__ __forceinline__ void ldsm4(uint32_t* r, uint32_t addr) {
    asm volatile("ldmatrix.sync.aligned.m8n8.x4.shared.b16 {%0,%1,%2,%3}, [%4];"
                 : "=r"(r[0]), "=r"(r[1]), "=r"(r[2]), "=r"(r[3]) : "r"(addr));
}
static __device__ __forceinline__ void ldsm4t(uint32_t* r, uint32_t addr) {
    asm volatile("ldmatrix.sync.aligned.m8n8.x4.trans.shared.b16 {%0,%1,%2,%3}, [%4];"
                 : "=r"(r[0]), "=r"(r[1]), "=r"(r[2]), "=r"(r[3]) : "r"(addr));
}
static __device__ __forceinline__ void mma16816(float* c, const uint32_t* a,
                                                const uint32_t* b) {
    asm volatile(
        "mma.sync.aligned.m16n8k16.row.col.f32.bf16.bf16.f32 "
        "{%0,%1,%2,%3}, {%4,%5,%6,%7}, {%8,%9}, {%0,%1,%2,%3};"
        : "+f"(c[0]), "+f"(c[1]), "+f"(c[2]), "+f"(c[3])
        : "r"(a[0]), "r"(a[1]), "r"(a[2]), "r"(a[3]), "r"(b[0]), "r"(b[1]));
}
static __device__ __forceinline__ unsigned long long pack2(float x, float y) {
    unsigned long long r;
    asm("mov.b64 %0, {%1, %2};" : "=l"(r) : "f"(x), "f"(y));
    return r;
}
static __device__ __forceinline__ void fma2(unsigned long long& d,
                                            unsigned long long a,
                                            unsigned long long b) {
    asm("fma.rn.f32x2 %0, %1, %2, %0;" : "+l"(d) : "l"(a), "l"(b));
}
static __device__ __forceinline__ float2 unpack2(unsigned long long v) {
    float2 r;
    asm("mov.b64 {%0, %1}, %2;" : "=f"(r.x), "=f"(r.y) : "l"(v));
    return r;
}
static __device__ __forceinline__ void cvt4(float4 v, uint2& hi, uint2& lo) {
    __nv_bfloat162 h0 = __floats2bfloat162_rn(v.x, v.y);
    __nv_bfloat162 h1 = __floats2bfloat162_rn(v.z, v.w);
    uint32_t u0 = *(uint32_t*)&h0;
    uint32_t u1 = *(uint32_t*)&h1;
    float rx = v.x - __uint_as_float(u0 << 16);
    float ry = v.y - __uint_as_float(u0 & 0xffff0000u);
    float rz = v.z - __uint_as_float(u1 << 16);
    float rw = v.w - __uint_as_float(u1 & 0xffff0000u);
    __nv_bfloat162 l0 = __floats2bfloat162_rn(rx, ry);
    __nv_bfloat162 l1 = __floats2bfloat162_rn(rz, rw);
    hi = make_uint2(u0, u1);
    lo = make_uint2(*(uint32_t*)&l0, *(uint32_t*)&l1);
}
static __device__ __forceinline__ uint32_t a_sts(int f) {
    const uint32_t b = (uint32_t)f >> 3, k4 = (uint32_t)f & 7u;
    return b * 64u + (((k4 >> 1) ^ ((b >> 1) & 3u)) << 4) + ((k4 & 1u) << 3);
}
static __device__ __forceinline__ uint32_t b_sts(uint32_t row, uint32_t n4) {
    return row * 512u + ((((n4 >> 1) ^ (row & 7u))) << 4) + ((n4 & 1u) << 3);
}

// one ffma k-step (k = j within current 8-row chunk), injected into MMA phase
#define FFSTEP(j) do { if (do_f) {                                               \
    const char* _fb = smem + FF_BANK + (uint32_t)p * 8192u +                     \
                      (uint32_t)(j) * 1024u + (uint32_t)lane * 16u;              \
    const ulonglong2 _v0 = *(const ulonglong2*)_fb;                              \
    const ulonglong2 _v1 = *(const ulonglong2*)(_fb + 512);                      \
    if (w == 0) {                                                                \
        fma2(nrmf[0], _v0.x, _v0.x); fma2(nrmf[1], _v0.y, _v0.y);                \
        fma2(nrmf[2], _v1.x, _v1.x); fma2(nrmf[3], _v1.y, _v1.y);                \
    }                                                                            \
    const float _cp = ((j) & 3) == 0 ? ctf.x : ((j) & 3) == 1 ? ctf.y :          \
                      ((j) & 3) == 2 ? ctf.z : ctf.w;                            \
    _Pragma("unroll")                                                            \
    for (int _i = 0; _i < 8; ++_i) {                                             \
        const float _c = __shfl_sync(0xffffffffu, _cp, _i * 2 + ((j) >> 2));     \
        const unsigned long long _c2 = pack2(_c, _c);                            \
        fma2(accf[_i][0], _c2, _v0.x); fma2(accf[_i][1], _c2, _v0.y);            \
        fma2(accf[_i][2], _c2, _v1.x); fma2(accf[_i][3], _c2, _v1.y);            \
    } } } while (0)

__global__ void __launch_bounds__(256)
sim_dual_kernel(const float* __restrict__ content, const float* __restrict__ bank) {
    extern __shared__ char smem[];
    const uint32_t sbase = smem_u32(smem);
    const int tid = threadIdx.x, lane = tid & 31, w = tid >> 5, bid = blockIdx.x;

    const int tbase = NTT / NCTA, trem = NTT % NCTA;
    const int t0 = bid * tbase + (bid < trem ? bid : trem);
    const int nt = tbase + (bid < trem ? 1 : 0);
    const int ntT = (nt * 4 + 4) / 5;          // tensor tiles
    const int nF  = (nt - ntT) * 4;            // ffma 8-row chunks
    const long long kF0 = (long long)(t0 + ntT) * KT;

    // tensor indices
    const int n4 = tid & 63, kq = tid >> 6, lr = lane & 15, lc = lane >> 4;
    uint32_t bsts[8];
    #pragma unroll
    for (int i = 0; i < 8; ++i) bsts[i] = b_sts((uint32_t)(i * 4 + kq), (uint32_t)n4);
    const int ct_b0 = tid >> 3, ct_k4 = tid & 7, ct_b1 = (256 + tid) >> 3;
    const uint32_t asts0 = a_sts(tid), asts1 = a_sts(256 + tid);
    uint32_t aoff[2][4], boff[2][2];
    #pragma unroll
    for (int kk = 0; kk < 2; ++kk) {
        #pragma unroll
        for (int fm = 0; fm < 4; ++fm)
            aoff[kk][fm] = (uint32_t)(fm * 16 + lr) * 64u +
                ((((uint32_t)(kk * 2 + lc)) ^ (((uint32_t)lr >> 1) & 3u)) << 4);
        #pragma unroll
        for (int g = 0; g < 2; ++g)
            boff[kk][g] = (uint32_t)(kk * 16 + lr) * 512u +
                ((((uint32_t)(w * 4 + g * 2 + lc)) ^ ((uint32_t)lr & 7u)) << 4);
    }

    float acc[4][4][4];
    #pragma unroll
    for (int i = 0; i < 4; ++i)
        #pragma unroll
        for (int j = 0; j < 4; ++j)
            #pragma unroll
            for (int k = 0; k < 4; ++k) acc[i][j][k] = 0.f;
    unsigned long long accf[8][4];
    #pragma unroll
    for (int i = 0; i < 8; ++i)
        #pragma unroll
        for (int k = 0; k < 4; ++k) accf[i][k] = 0ULL;
    unsigned long long nrmf[4] = {0ULL, 0ULL, 0ULL, 0ULL};
    float4 nrm = make_float4(0.f, 0.f, 0.f, 0.f);

    float4 bkreg[8], ctreg[2];   // tensor staging
    float4 bkf0, bkf1, ctf;      // ffma staging

    // ---- prologue: tensor tile 0 -> buf0; ffma chunk 0 -> fbuf0 ----
    {
        const long long d0 = (long long)t0 * KT;
        const float4* bs = (const float4*)bank + d0 * 64;
        #pragma unroll
        for (int i = 0; i < 8; ++i) bkreg[i] = bs[(i * 4 + kq) * 64 + n4];
        ctreg[0] = *(const float4*)(content + (long long)ct_b0 * DLL + d0 + ct_k4 * 4);
        ctreg[1] = *(const float4*)(content + (long long)ct_b1 * DLL + d0 + ct_k4 * 4);
        #pragma unroll
        for (int i = 0; i < 8; ++i) {
            uint2 hi, lo;
            cvt4(bkreg[i], hi, lo);
            *(uint2*)(smem + B_HI + bsts[i]) = hi;
            *(uint2*)(smem + B_LO + bsts[i]) = lo;
            nrm.x = fmaf(bkreg[i].x, bkreg[i].x, nrm.x);
            nrm.y = fmaf(bkreg[i].y, bkreg[i].y, nrm.y);
            nrm.z = fmaf(bkreg[i].z, bkreg[i].z, nrm.z);
            nrm.w = fmaf(bkreg[i].w, bkreg[i].w, nrm.w);
        }
        uint2 hi, lo;
        cvt4(ctreg[0], hi, lo);
        *(uint2*)(smem + A_HI + asts0) = hi;
        *(uint2*)(smem + A_LO + asts0) = lo;
        cvt4(ctreg[1], hi, lo);
        *(uint2*)(smem + A_HI + asts1) = hi;
        *(uint2*)(smem + A_LO + asts1) = lo;
        // ffma chunk 0
        const float4* fb = (const float4*)(bank + kF0 * MB);
        bkf0 = fb[tid];
        bkf1 = fb[tid + 256];
        *(float4*)(smem + FF_BANK + (uint32_t)tid * 16u) = bkf0;
        *(float4*)(smem + FF_BANK + (uint32_t)(tid + 256) * 16u) = bkf1;
        if (lane < 16)
            ctf = *(const float4*)(content + (long long)(w * 8 + (lane >> 1)) * DLL +
                                   kF0 + (lane & 1) * 4);
    }
    __syncthreads();

    for (int t = 0; t < ntT; ++t) {
        const int p = t & 1;
        const bool more   = (t + 1 < ntT);
        const bool do_f   = (t < nF);
        const bool more_f = (t + 1 < nF);

        // 1) tensor LDG(t+1) + ffma bank LDG(t+1)
        if (more) {
            const long long d0n = (long long)(t0 + t + 1) * KT;
            const float4* bs = (const float4*)bank + d0n * 64;
            #pragma unroll
            for (int i = 0; i < 8; ++i) bkreg[i] = bs[(i * 4 + kq) * 64 + n4];
            ctreg[0] = *(const float4*)(content + (long long)ct_b0 * DLL + d0n + ct_k4 * 4);
            ctreg[1] = *(const float4*)(content + (long long)ct_b1 * DLL + d0n + ct_k4 * 4);
        }
        if (more_f) {
            const float4* fb = (const float4*)(bank + (kF0 + (long long)(t + 1) * 8) * MB);
            bkf0 = fb[tid];
            bkf1 = fb[tid + 256];
        }

        // 2) MMA(t) with FFMA chunk(t) injected
        {
            const uint32_t bb = sbase + (uint32_t)p * BUFB;
            #pragma unroll
            for (int kk = 0; kk < 2; ++kk) {
                uint32_t ah[4][4];
                #pragma unroll
                for (int fm = 0; fm < 4; ++fm)
                    ldsm4(ah[fm], bb + A_HI + aoff[kk][fm]);
                uint32_t bh[4][2];
                {
                    uint32_t r[4];
                    ldsm4t(r, bb + B_HI + boff[kk][0]);
                    bh[0][0] = r[0]; bh[0][1] = r[1]; bh[1][0] = r[2]; bh[1][1] = r[3];
                    ldsm4t(r, bb + B_HI + boff[kk][1]);
                    bh[2][0] = r[0]; bh[2][1] = r[1]; bh[3][0] = r[2]; bh[3][1] = r[3];
                }
                FFSTEP(kk * 4 + 0);
                #pragma unroll
                for (int fm = 0; fm < 4; ++fm)
                    #pragma unroll
                    for (int fn = 0; fn < 4; ++fn)
                        mma16816(acc[fm][fn], ah[fm], bh[fn]);
                FFSTEP(kk * 4 + 1);
                uint32_t bl[4][2];
                {
                    uint32_t r[4];
                    ldsm4t(r, bb + B_LO + boff[kk][0]);
                    bl[0][0] = r[0]; bl[0][1] = r[1]; bl[1][0] = r[2]; bl[1][1] = r[3];
                    ldsm4t(r, bb + B_LO + boff[kk][1]);
                    bl[2][0] = r[0]; bl[2][1] = r[1]; bl[3][0] = r[2]; bl[3][1] = r[3];
                }
                #pragma unroll
                for (int fm = 0; fm < 4; ++fm)
                    #pragma unroll
                    for (int fn = 0; fn < 4; ++fn)
                        mma16816(acc[fm][fn], ah[fm], bl[fn]);
                FFSTEP(kk * 4 + 2);
                #pragma unroll
                for (int fm = 0; fm < 4; ++fm) {
                    uint32_t al[4];
                    ldsm4(al, bb + A_LO + aoff[kk][fm]);
                    #pragma unroll
                    for (int fn = 0; fn < 4; ++fn)
                        mma16816(acc[fm][fn], al, bh[fn]);
                }
                FFSTEP(kk * 4 + 3);
            }
        }

        // 3) tensor cvt+STS(t+1); ffma STS(t+1) + content LDG(t+1)
        if (more) {
            char* buf = smem + (uint32_t)(p ^ 1) * BUFB;
            #pragma unroll
            for (int i = 0; i < 8; ++i) {
                uint2 hi, lo;
                cvt4(bkreg[i], hi, lo);
                *(uint2*)(buf + B_HI + bsts[i]) = hi;
                *(uint2*)(buf + B_LO + bsts[i]) = lo;
                nrm.x = fmaf(bkreg[i].x, bkreg[i].x, nrm.x);
                nrm.y = fmaf(bkreg[i].y, bkreg[i].y, nrm.y);
                nrm.z = fmaf(bkreg[i].z, bkreg[i].z, nrm.z);
                nrm.w = fmaf(bkreg[i].w, bkreg[i].w, nrm.w);
            }
            uint2 hi, lo;
            cvt4(ctreg[0], hi, lo);
            *(uint2*)(buf + A_HI + asts0) = hi;
            *(uint2*)(buf + A_LO + asts0) = lo;
            cvt4(ctreg[1], hi, lo);
            *(uint2*)(buf + A_HI + asts1) = hi;
            *(uint2*)(buf + A_LO + asts1) = lo;
        }
        if (more_f) {
            char* fbuf = smem + FF_BANK + (uint32_t)(p ^ 1) * 8192u;
            *(float4*)(fbuf + (uint32_t)tid * 16u) = bkf0;
            *(float4*)(fbuf + (uint32_t)(tid + 256) * 16u) = bkf1;
            if (lane < 16)
                ctf = *(const float4*)(content + (long long)(w * 8 + (lane >> 1)) * DLL +
                                       kF0 + (long long)(t + 1) * 8 + (lane & 1) * 4);
        }
        __syncthreads();
    }

    // ---- tensor norm reduce + write (chunk bid) ----
    ((float4*)smem)[tid] = nrm;
    __syncthreads();
    if (tid < 64) {
        const float4* n = (const float4*)smem;
        float4 s0 = n[tid], s1 = n[tid + 64], s2 = n[tid + 128], s3 = n[tid + 192];
        float4 s = make_float4(s0.x + s1.x + s2.x + s3.x, s0.y + s1.y + s2.y + s3.y,
                               s0.z + s1.z + s2.z + s3.z, s0.w + s1.w + s2.w + s3.w);
        *(float4*)(g_pnorm + (size_t)bid * MB + tid * 4) = s;
    }
    // ---- tensor psim write (chunk bid) ----
    {
        float* ps = g_psim + (size_t)bid * (BQ * MB);
        const int gr = lane >> 2, c2 = (lane & 3) * 2;
        #pragma unroll
        for (int fm = 0; fm < 4; ++fm)
            #pragma unroll
            for (int fn = 0; fn < 4; ++fn) {
                const int b0 = fm * 16 + gr;
                const int n = w * 32 + fn * 8 + c2;
                *(float2*)&ps[b0 * MB + n] = make_float2(acc[fm][fn][0], acc[fm][fn][1]);
                *(float2*)&ps[(b0 + 8) * MB + n] = make_float2(acc[fm][fn][2], acc[fm][fn][3]);
            }
    }
    // ---- ffma psim + norm write (chunk NCTA+bid) ----
    {
        float* ps2 = g_psim + (size_t)(NCTA + bid) * (BQ * MB);
        #pragma unroll
        for (int i = 0; i < 8; ++i) {
            const int b = w * 8 + i;
            float2 q0 = unpack2(accf[i][0]), q1 = unpack2(accf[i][1]);
            float2 q2 = unpack2(accf[i][2]), q3 = unpack2(accf[i][3]);
            *(float4*)&ps2[b * MB + lane * 4] = make_float4(q0.x, q0.y, q1.x, q1.y);
            *(float4*)&ps2[b * MB + 128 + lane * 4] = make_float4(q2.x, q2.y, q3.x, q3.y);
        }
        if (w == 0) {
            float* pn2 = g_pnorm + (size_t)(NCTA + bid) * MB;
            float2 q0 = unpack2(nrmf[0]), q1 = unpack2(nrmf[1]);
            float2 q2 = unpack2(nrmf[2]), q3 = unpack2(nrmf[3]);
            *(float4*)&pn2[lane * 4] = make_float4(q0.x, q0.y, q1.x, q1.y);
            *(float4*)&pn2[128 + lane * 4] = make_float4(q2.x, q2.y, q3.x, q3.y);
        }
    }
}

// reduce partials over 2*NCTA chunks -> argmax -> gather
__global__ __launch_bounds__(1024)
void argmax_gather_kernel(const float* __restrict__ style,
                          float* __restrict__ out) {
    const int b = blockIdx.x, tid = threadIdx.x;
    const int m = tid & 255, q = tid >> 8;
    const int CPQ = (2 * NCTA) / 4;   // 76

    float sim = 0.f, n2 = 0.f;
    const int c0 = q * CPQ;
    for (int c = c0; c < c0 + CPQ; ++c) {
        sim += g_psim[(size_t)c * (BQ * MB) + b * MB + m];
        n2  += g_pnorm[(size_t)c * MB + m];
    }

    __shared__ float s_sim[4][256];
    __shared__ float s_n2[4][256];
    s_sim[q][m] = sim;
    s_n2[q][m] = n2;
    __syncthreads();

    __shared__ float s_val[256];
    __shared__ int s_idx[256];
    if (q == 0) {
        const float st = s_sim[0][m] + s_sim[1][m] + s_sim[2][m] + s_sim[3][m];
        const float nt2 = s_n2[0][m] + s_n2[1][m] + s_n2[2][m] + s_n2[3][m];
        s_val[m] = st / fmaxf(sqrtf(nt2), 1e-12f);
        s_idx[m] = m;
    }
    __syncthreads();

    #pragma unroll
    for (int s = 128; s > 0; s >>= 1) {
        if (tid < s) {
            const float v1 = s_val[tid + s], v0 = s_val[tid];
            const int i1 = s_idx[tid + s], i0 = s_idx[tid];
            if (v1 > v0 || (v1 == v0 && i1 < i0)) { s_val[tid] = v1; s_idx[tid] = i1; }
        }
        __syncthreads();
    }
    const int idx = s_idx[0];

    const float2* src = (const float2*)(style + (size_t)idx * SDIM);
    float2* dst = (float2*)(out + (size_t)b * SDIM);
    dst[tid] = src[tid];
}

extern "C" void kernel_launch(void* const* d_in, const int* in_sizes, int n_in,
                              void* d_out, int out_size) {
    const float* content = (const float*)d_in[0];
    const float* bank    = (const float*)d_in[1];
    const float* style   = (const float*)d_in[2];
    float* out = (float*)d_out;

    cudaFuncSetAttribute(sim_dual_kernel,
                         cudaFuncAttributeMaxDynamicSharedMemorySize, SMEM_TOTAL);

    sim_dual_kernel<<<NCTA, 256, SMEM_TOTAL>>>(content, bank);
    argmax_gather_kernel<<<BQ, 1024>>>(style, out);
}

// round 10
// speedup vs baseline: 1.4415x; 1.4415x over previous
#include <cuda_runtime.h>
#include <cuda_fp16.h>
#include <cstdint>

// ---------------- problem constants ----------------
#define BQ 64            // batch (GEMM M)
#define MB 256           // bank entries (GEMM N)
#define DLL 524288LL     // feature dim K
#define KT 32            // K per tile
#define NTT 16384        // DLL / KT
#define NCTA 152         // 1 CTA per SM
#define SDIM 2048        // style dim

// static scratch
__device__ float g_psim[NCTA * BQ * MB];   // [cta][b][m]
__device__ float g_pnorm[NCTA * MB];       // [cta][m]

// ---------------- smem layout (bytes, per buffer) ----------------
// A (content): [64 b][k pitch 40] fp16 -> 64*80 = 5120 B  (hi, lo)
// B (bank)   : [32 k][n pitch 264] fp16 -> 32*528 = 16896 B (hi only)
#define A_HI 0u
#define A_LO 5120u
#define B_HI 10240u
#define BUFB 27648u
#define SMEM_TOTAL (2u * BUFB)   // 55296

// ---------------- helpers ----------------
static __device__ __forceinline__ uint32_t smem_u32(const void* p) {
    uint32_t a;
    asm("{ .reg .u64 t; cvta.to.shared.u64 t, %1; cvt.u32.u64 %0, t; }"
        : "=r"(a) : "l"(p));
    return a;
}
static __device__ __forceinline__ void ldsm4(uint32_t* r, uint32_t addr) {
    asm volatile("ldmatrix.sync.aligned.m8n8.x4.shared.b16 {%0,%1,%2,%3}, [%4];"
                 : "=r"(r[0]), "=r"(r[1]), "=r"(r[2]), "=r"(r[3]) : "r"(addr));
}
static __device__ __forceinline__ void ldsm4t(uint32_t* r, uint32_t addr) {
    asm volatile("ldmatrix.sync.aligned.m8n8.x4.trans.shared.b16 {%0,%1,%2,%3}, [%4];"
                 : "=r"(r[0]), "=r"(r[1]), "=r"(r[2]), "=r"(r[3]) : "r"(addr));
}
static __device__ __forceinline__ void mma16816(float* c, const uint32_t* a,
                                                const uint32_t* b) {
    asm volatile(
        "mma.sync.aligned.m16n8k16.row.col.f32.f16.f16.f32 "
        "{%0,%1,%2,%3}, {%4,%5,%6,%7}, {%8,%9}, {%0,%1,%2,%3};"
        : "+f"(c[0]), "+f"(c[1]), "+f"(c[2]), "+f"(c[3])
        : "r"(a[0]), "r"(a[1]), "r"(a[2]), "r"(a[3]), "r"(b[0]), "r"(b[1]));
}

// fp32x4 -> fp16 hi/lo pairs (A side: hi = rn16(a), lo = rn16(a - hi))
static __device__ __forceinline__ void cvt4h(float4 v, uint2& hi, uint2& lo) {
    __half2 h0 = __floats2half2_rn(v.x, v.y);
    __half2 h1 = __floats2half2_rn(v.z, v.w);
    float2 f0 = __half22float2(h0);
    float2 f1 = __half22float2(h1);
    __half2 l0 = __floats2half2_rn(v.x - f0.x, v.y - f0.y);
    __half2 l1 = __floats2half2_rn(v.z - f1.x, v.w - f1.y);
    hi = make_uint2(*(uint32_t*)&h0, *(uint32_t*)&h1);
    lo = make_uint2(*(uint32_t*)&l0, *(uint32_t*)&l1);
}
// fp32x4 -> fp16x4 (B side: single term)
static __device__ __forceinline__ uint2 cvt4s(float4 v) {
    __half2 h0 = __floats2half2_rn(v.x, v.y);
    __half2 h1 = __floats2half2_rn(v.z, v.w);
    return make_uint2(*(uint32_t*)&h0, *(uint32_t*)&h1);
}

// =====================================================================
// Kernel 1: split-K fp16 2-term mma.sync GEMM + exact fp32 norm^2.
// grid = NCTA, 256 threads (8 warps). Warp w owns b[0..64) x n[w*32,+32).
// Structure identical to the proven R3 pipeline; only term count changes.
// =====================================================================
__global__ void __launch_bounds__(256)
sim_mma_kernel(const float* __restrict__ content, const float* __restrict__ bank) {
    extern __shared__ char smem[];
    const uint32_t sbase = smem_u32(smem);
    const int tid  = threadIdx.x;
    const int lane = tid & 31;
    const int w    = tid >> 5;
    const int bid  = blockIdx.x;

    const int tbase = NTT / NCTA;                 // 107
    const int trem  = NTT % NCTA;                 // 120
    const int t0 = bid * tbase + (bid < trem ? bid : trem);
    const int nt = tbase + (bid < trem ? 1 : 0);

    const int n4 = tid & 63;      // bank float4 column
    const int kq = tid >> 6;      // 0..3
    const int lr = lane & 15;
    const int lc = lane >> 4;

    const uint32_t bsts = (uint32_t)kq * 528u + (uint32_t)n4 * 8u;
    const int ct_b0 = tid >> 3, ct_k4 = tid & 7;
    const int ct_b1 = (256 + tid) >> 3;
    const uint32_t asts0 = (uint32_t)ct_b0 * 80u + (uint32_t)ct_k4 * 8u;
    const uint32_t asts1 = (uint32_t)ct_b1 * 80u + (uint32_t)ct_k4 * 8u;

    float acc[4][4][4];
    #pragma unroll
    for (int i = 0; i < 4; ++i)
        #pragma unroll
        for (int j = 0; j < 4; ++j)
            #pragma unroll
            for (int k = 0; k < 4; ++k) acc[i][j][k] = 0.f;
    float4 nrm = make_float4(0.f, 0.f, 0.f, 0.f);

    float4 bkreg[8];
    float4 ctreg[2];

    // ---- prologue: LDG(0), cvt+STS(0) -> buf0, sync ----
    {
        const long long d0 = (long long)t0 * KT;
        const float4* bs = (const float4*)bank + d0 * 64;
        #pragma unroll
        for (int i = 0; i < 8; ++i) bkreg[i] = bs[(i * 4 + kq) * 64 + n4];
        ctreg[0] = *(const float4*)(content + (long long)ct_b0 * DLL + d0 + ct_k4 * 4);
        ctreg[1] = *(const float4*)(content + (long long)ct_b1 * DLL + d0 + ct_k4 * 4);

        char* buf = smem;
        #pragma unroll
        for (int i = 0; i < 8; ++i) {
            *(uint2*)(buf + B_HI + bsts + (uint32_t)i * (4u * 528u)) = cvt4s(bkreg[i]);
            nrm.x = fmaf(bkreg[i].x, bkreg[i].x, nrm.x);
            nrm.y = fmaf(bkreg[i].y, bkreg[i].y, nrm.y);
            nrm.z = fmaf(bkreg[i].z, bkreg[i].z, nrm.z);
            nrm.w = fmaf(bkreg[i].w, bkreg[i].w, nrm.w);
        }
        uint2 hi, lo;
        cvt4h(ctreg[0], hi, lo);
        *(uint2*)(buf + A_HI + asts0) = hi;
        *(uint2*)(buf + A_LO + asts0) = lo;
        cvt4h(ctreg[1], hi, lo);
        *(uint2*)(buf + A_HI + asts1) = hi;
        *(uint2*)(buf + A_LO + asts1) = lo;
    }
    __syncthreads();

    for (int t = 0; t < nt; ++t) {
        const int p = t & 1;
        const bool more = (t + 1 < nt);

        // 1) LDG(t+1)
        if (more) {
            const long long d0n = (long long)(t0 + t + 1) * KT;
            const float4* bs = (const float4*)bank + d0n * 64;
            #pragma unroll
            for (int i = 0; i < 8; ++i) bkreg[i] = bs[(i * 4 + kq) * 64 + n4];
            ctreg[0] = *(const float4*)(content + (long long)ct_b0 * DLL + d0n + ct_k4 * 4);
            ctreg[1] = *(const float4*)(content + (long long)ct_b1 * DLL + d0n + ct_k4 * 4);
        }

        // 2) MMA(t) on buf p: 2 terms (Ah*Bh, Al*Bh)
        {
            const uint32_t bb = sbase + (uint32_t)p * BUFB;
            #pragma unroll
            for (int kk = 0; kk < 2; ++kk) {
                uint32_t ah[4][4], al[4][4];
                #pragma unroll
                for (int fm = 0; fm < 4; ++fm) {
                    const uint32_t aoff = (uint32_t)(fm * 16 + lr) * 80u +
                                          (uint32_t)(kk * 16 + lc * 8) * 2u;
                    ldsm4(ah[fm], bb + A_HI + aoff);
                    ldsm4(al[fm], bb + A_LO + aoff);
                }
                uint32_t bh[4][2];
                #pragma unroll
                for (int g = 0; g < 2; ++g) {
                    const uint32_t boff = (uint32_t)(kk * 16 + lr) * 528u +
                                          (uint32_t)(w * 32 + g * 16 + lc * 8) * 2u;
                    uint32_t r[4];
                    ldsm4t(r, bb + B_HI + boff);
                    bh[g * 2][0] = r[0]; bh[g * 2][1] = r[1];
                    bh[g * 2 + 1][0] = r[2]; bh[g * 2 + 1][1] = r[3];
                }
                #pragma unroll
                for (int fm = 0; fm < 4; ++fm)
                    #pragma unroll
                    for (int fn = 0; fn < 4; ++fn) {
                        mma16816(acc[fm][fn], ah[fm], bh[fn]);   // hi*hi
                        mma16816(acc[fm][fn], al[fm], bh[fn]);   // lo*hi
                    }
            }
        }

        // 3) cvt+STS(t+1) into the other buffer
        if (more) {
            char* buf = smem + (uint32_t)(p ^ 1) * BUFB;
            #pragma unroll
            for (int i = 0; i < 8; ++i) {
                *(uint2*)(buf + B_HI + bsts + (uint32_t)i * (4u * 528u)) = cvt4s(bkreg[i]);
                nrm.x = fmaf(bkreg[i].x, bkreg[i].x, nrm.x);
                nrm.y = fmaf(bkreg[i].y, bkreg[i].y, nrm.y);
                nrm.z = fmaf(bkreg[i].z, bkreg[i].z, nrm.z);
                nrm.w = fmaf(bkreg[i].w, bkreg[i].w, nrm.w);
            }
            uint2 hi, lo;
            cvt4h(ctreg[0], hi, lo);
            *(uint2*)(buf + A_HI + asts0) = hi;
            *(uint2*)(buf + A_LO + asts0) = lo;
            cvt4h(ctreg[1], hi, lo);
            *(uint2*)(buf + A_HI + asts1) = hi;
            *(uint2*)(buf + A_LO + asts1) = lo;
        }

        __syncthreads();
    }

    // ---- norm^2 reduce across the 4 k-quarters ----
    ((float4*)smem)[tid] = nrm;
    __syncthreads();
    if (tid < 64) {
        const float4* n = (const float4*)smem;
        float4 s0 = n[tid], s1 = n[tid + 64], s2 = n[tid + 128], s3 = n[tid + 192];
        float4 s = make_float4(s0.x + s1.x + s2.x + s3.x,
                               s0.y + s1.y + s2.y + s3.y,
                               s0.z + s1.z + s2.z + s3.z,
                               s0.w + s1.w + s2.w + s3.w);
        *(float4*)(g_pnorm + (size_t)bid * MB + tid * 4) = s;
    }

    // ---- psim write ----
    {
        float* ps = g_psim + (size_t)bid * (BQ * MB);
        const int gr = lane >> 2, c2 = (lane & 3) * 2;
        #pragma unroll
        for (int fm = 0; fm < 4; ++fm)
            #pragma unroll
            for (int fn = 0; fn < 4; ++fn) {
                const int b0 = fm * 16 + gr;
                const int n  = w * 32 + fn * 8 + c2;
                *(float2*)&ps[b0 * MB + n] =
                    make_float2(acc[fm][fn][0], acc[fm][fn][1]);
                *(float2*)&ps[(b0 + 8) * MB + n] =
                    make_float2(acc[fm][fn][2], acc[fm][fn][3]);
            }
    }
}

// =====================================================================
// Kernel 2: reduce partials -> score -> argmax -> gather style row.
// =====================================================================
__global__ __launch_bounds__(1024)
void argmax_gather_kernel(const float* __restrict__ style,
                          float* __restrict__ out) {
    const int b   = blockIdx.x;
    const int tid = threadIdx.x;
    const int m   = tid & 255;
    const int q   = tid >> 8;
    const int CPQ = NCTA / 4;            // 38

    float sim = 0.f, n2 = 0.f;
    const int c0 = q * CPQ;
    for (int c = c0; c < c0 + CPQ; ++c) {
        sim += g_psim[(size_t)c * (BQ * MB) + b * MB + m];
        n2  += g_pnorm[(size_t)c * MB + m];
    }

    __shared__ float s_sim[4][256];
    __shared__ float s_n2[4][256];
    s_sim[q][m] = sim;
    s_n2[q][m]  = n2;
    __syncthreads();

    __shared__ float s_val[256];
    __shared__ int   s_idx[256];
    if (q == 0) {
        const float st = s_sim[0][m] + s_sim[1][m] + s_sim[2][m] + s_sim[3][m];
        const float nt = s_n2[0][m]  + s_n2[1][m]  + s_n2[2][m]  + s_n2[3][m];
        const float norm = fmaxf(sqrtf(nt), 1e-12f);
        s_val[m] = st / norm;
        s_idx[m] = m;
    }
    __syncthreads();

    #pragma unroll
    for (int s = 128; s > 0; s >>= 1) {
        if (tid < s) {
            const float v1 = s_val[tid + s], v0 = s_val[tid];
            const int   i1 = s_idx[tid + s], i0 = s_idx[tid];
            if (v1 > v0 || (v1 == v0 && i1 < i0)) {
                s_val[tid] = v1;
                s_idx[tid] = i1;
            }
        }
        __syncthreads();
    }
    const int idx = s_idx[0];

    const float2* src = (const float2*)(style + (size_t)idx * SDIM);
    float2* dst = (float2*)(out + (size_t)b * SDIM);
    dst[tid] = src[tid];
}

extern "C" void kernel_launch(void* const* d_in, const int* in_sizes, int n_in,
                              void* d_out, int out_size) {
    const float* content = (const float*)d_in[0];
    const float* bank    = (const float*)d_in[1];
    const float* style   = (const float*)d_in[2];
    float* out = (float*)d_out;

    cudaFuncSetAttribute(sim_mma_kernel,
                         cudaFuncAttributeMaxDynamicSharedMemorySize, SMEM_TOTAL);

    sim_mma_kernel<<<NCTA, 256, SMEM_TOTAL>>>(content, bank);
    argmax_gather_kernel<<<BQ, 1024>>>(style, out);
}

// round 11
// speedup vs baseline: 1.4836x; 1.0292x over previous
#include <cuda_runtime.h>
#include <cuda_fp16.h>
#include <cstdint>

// ---------------- problem constants ----------------
#define BQ 64            // batch (GEMM M)
#define MB 256           // bank entries (GEMM N)
#define DLL 524288LL     // feature dim K
#define KT 32            // K per tile
#define NTT 16384        // DLL / KT
#define NCTA 152         // 1 CTA per SM
#define SDIM 2048        // style dim

// static scratch
__device__ float g_psim[NCTA * BQ * MB];   // [cta][b][m]
__device__ float g_pnorm[NCTA * MB];       // [cta][m]

// ---------------- smem layout (bytes, per buffer) ----------------
// A (content): [64 b][k pitch 40] fp16 -> 64*80 = 5120 B  (hi, lo)
// B (bank)   : [32 k][n pitch 264] fp16 -> 32*528 = 16896 B (hi only)
#define A_HI 0u
#define A_LO 5120u
#define B_HI 10240u
#define BUFB 27648u
#define SMEM_TOTAL (2u * BUFB)   // 55296

// ---------------- helpers ----------------
static __device__ __forceinline__ uint32_t smem_u32(const void* p) {
    uint32_t a;
    asm("{ .reg .u64 t; cvta.to.shared.u64 t, %1; cvt.u32.u64 %0, t; }"
        : "=r"(a) : "l"(p));
    return a;
}
static __device__ __forceinline__ void ldsm4(uint32_t* r, uint32_t addr) {
    asm volatile("ldmatrix.sync.aligned.m8n8.x4.shared.b16 {%0,%1,%2,%3}, [%4];"
                 : "=r"(r[0]), "=r"(r[1]), "=r"(r[2]), "=r"(r[3]) : "r"(addr));
}
static __device__ __forceinline__ void ldsm4t(uint32_t* r, uint32_t addr) {
    asm volatile("ldmatrix.sync.aligned.m8n8.x4.trans.shared.b16 {%0,%1,%2,%3}, [%4];"
                 : "=r"(r[0]), "=r"(r[1]), "=r"(r[2]), "=r"(r[3]) : "r"(addr));
}
static __device__ __forceinline__ void mma16816(float* c, const uint32_t* a,
                                                const uint32_t* b) {
    asm volatile(
        "mma.sync.aligned.m16n8k16.row.col.f32.f16.f16.f32 "
        "{%0,%1,%2,%3}, {%4,%5,%6,%7}, {%8,%9}, {%0,%1,%2,%3};"
        : "+f"(c[0]), "+f"(c[1]), "+f"(c[2]), "+f"(c[3])
        : "r"(a[0]), "r"(a[1]), "r"(a[2]), "r"(a[3]), "r"(b[0]), "r"(b[1]));
}
// fp32x4 -> fp16 hi/lo pairs (A side)
static __device__ __forceinline__ void cvt4h(float4 v, uint2& hi, uint2& lo) {
    __half2 h0 = __floats2half2_rn(v.x, v.y);
    __half2 h1 = __floats2half2_rn(v.z, v.w);
    float2 f0 = __half22float2(h0);
    float2 f1 = __half22float2(h1);
    __half2 l0 = __floats2half2_rn(v.x - f0.x, v.y - f0.y);
    __half2 l1 = __floats2half2_rn(v.z - f1.x, v.w - f1.y);
    hi = make_uint2(*(uint32_t*)&h0, *(uint32_t*)&h1);
    lo = make_uint2(*(uint32_t*)&l0, *(uint32_t*)&l1);
}
// fp32x4 -> fp16x4 (B side, single term)
static __device__ __forceinline__ uint2 cvt4s(float4 v) {
    __half2 h0 = __floats2half2_rn(v.x, v.y);
    __half2 h1 = __floats2half2_rn(v.z, v.w);
    return make_uint2(*(uint32_t*)&h0, *(uint32_t*)&h1);
}

// =====================================================================
// Kernel 1: split-K fp16 2-term mma.sync GEMM, prefetch distance 2.
// grid = NCTA, 256 threads (8 warps). Warp w owns b[0..64) x n[w*32,+32).
//   step(t):  LDG(t+2) -> Rload ; MMA(t) on buf(t&1) ;
//             cvt+STS(t+1) from Rsts -> buf((t+1)&1) ; sync
// Register sets A/B ping-pong: LDG lands one full iteration before use.
// =====================================================================
__global__ void __launch_bounds__(256, 1)
sim_mma_kernel(const float* __restrict__ content, const float* __restrict__ bank) {
    extern __shared__ char smem[];
    const uint32_t sbase = smem_u32(smem);
    const int tid  = threadIdx.x;
    const int lane = tid & 31;
    const int w    = tid >> 5;
    const int bid  = blockIdx.x;

    const int tbase = NTT / NCTA;                 // 107
    const int trem  = NTT % NCTA;                 // 120
    const int t0 = bid * tbase + (bid < trem ? bid : trem);
    const int nt = tbase + (bid < trem ? 1 : 0);

    const int n4 = tid & 63;      // bank float4 column
    const int kq = tid >> 6;      // 0..3
    const int lr = lane & 15;
    const int lc = lane >> 4;

    const uint32_t bsts = (uint32_t)kq * 528u + (uint32_t)n4 * 8u;
    const int ct_b0 = tid >> 3, ct_k4 = tid & 7;
    const int ct_b1 = (256 + tid) >> 3;
    const uint32_t asts0 = (uint32_t)ct_b0 * 80u + (uint32_t)ct_k4 * 8u;
    const uint32_t asts1 = (uint32_t)ct_b1 * 80u + (uint32_t)ct_k4 * 8u;

    float acc[4][4][4];
    #pragma unroll
    for (int i = 0; i < 4; ++i)
        #pragma unroll
        for (int j = 0; j < 4; ++j)
            #pragma unroll
            for (int k = 0; k < 4; ++k) acc[i][j][k] = 0.f;
    float4 nrm = make_float4(0.f, 0.f, 0.f, 0.f);

    // two register staging sets (prefetch distance 2)
    float4 bkA[8], bkB[8];
    float4 ctA[2], ctB[2];

    // ---- tile load into a register set ----
    #define LDG_TILE(BK, CT, T) do {                                             \
        const long long _d0 = (long long)(t0 + (T)) * KT;                        \
        const float4* _bs = (const float4*)bank + _d0 * 64;                      \
        _Pragma("unroll")                                                        \
        for (int _i = 0; _i < 8; ++_i) (BK)[_i] = _bs[(_i * 4 + kq) * 64 + n4];  \
        (CT)[0] = *(const float4*)(content + (long long)ct_b0 * DLL + _d0 + ct_k4 * 4); \
        (CT)[1] = *(const float4*)(content + (long long)ct_b1 * DLL + _d0 + ct_k4 * 4); \
    } while (0)

    // ---- convert + STS a register set into buffer BUF (0/1) ----
    #define STS_TILE(BK, CT, BUF) do {                                           \
        char* _buf = smem + (uint32_t)(BUF) * BUFB;                              \
        _Pragma("unroll")                                                        \
        for (int _i = 0; _i < 8; ++_i) {                                         \
            *(uint2*)(_buf + B_HI + bsts + (uint32_t)_i * (4u * 528u)) = cvt4s((BK)[_i]); \
            nrm.x = fmaf((BK)[_i].x, (BK)[_i].x, nrm.x);                         \
            nrm.y = fmaf((BK)[_i].y, (BK)[_i].y, nrm.y);                         \
            nrm.z = fmaf((BK)[_i].z, (BK)[_i].z, nrm.z);                         \
            nrm.w = fmaf((BK)[_i].w, (BK)[_i].w, nrm.w);                         \
        }                                                                        \
        uint2 _hi, _lo;                                                          \
        cvt4h((CT)[0], _hi, _lo);                                                \
        *(uint2*)(_buf + A_HI + asts0) = _hi;                                    \
        *(uint2*)(_buf + A_LO + asts0) = _lo;                                    \
        cvt4h((CT)[1], _hi, _lo);                                                \
        *(uint2*)(_buf + A_HI + asts1) = _hi;                                    \
        *(uint2*)(_buf + A_LO + asts1) = _lo;                                    \
    } while (0)

    // ---- MMA a buffer into acc ----
    #define MMA_TILE(BUF) do {                                                   \
        const uint32_t _bb = sbase + (uint32_t)(BUF) * BUFB;                     \
        _Pragma("unroll")                                                        \
        for (int _kk = 0; _kk < 2; ++_kk) {                                      \
            uint32_t _ah[4][4], _al[4][4];                                       \
            _Pragma("unroll")                                                    \
            for (int _fm = 0; _fm < 4; ++_fm) {                                  \
                const uint32_t _ao = (uint32_t)(_fm * 16 + lr) * 80u +           \
                                     (uint32_t)(_kk * 16 + lc * 8) * 2u;         \
                ldsm4(_ah[_fm], _bb + A_HI + _ao);                               \
                ldsm4(_al[_fm], _bb + A_LO + _ao);                               \
            }                                                                    \
            uint32_t _bh[4][2];                                                  \
            _Pragma("unroll")                                                    \
            for (int _g = 0; _g < 2; ++_g) {                                     \
                const uint32_t _bo = (uint32_t)(_kk * 16 + lr) * 528u +          \
                                     (uint32_t)(w * 32 + _g * 16 + lc * 8) * 2u; \
                uint32_t _r[4];                                                  \
                ldsm4t(_r, _bb + B_HI + _bo);                                    \
                _bh[_g * 2][0] = _r[0]; _bh[_g * 2][1] = _r[1];                  \
                _bh[_g * 2 + 1][0] = _r[2]; _bh[_g * 2 + 1][1] = _r[3];          \
            }                                                                    \
            _Pragma("unroll")                                                    \
            for (int _fm = 0; _fm < 4; ++_fm)                                    \
                _Pragma("unroll")                                                \
                for (int _fn = 0; _fn < 4; ++_fn) {                              \
                    mma16816(acc[_fm][_fn], _ah[_fm], _bh[_fn]);                 \
                    mma16816(acc[_fm][_fn], _al[_fm], _bh[_fn]);                 \
                }                                                                \
        }                                                                        \
    } while (0)

    // ---- prologue: tile0 -> buf0 via A; tile1 -> B ----
    LDG_TILE(bkA, ctA, 0);
    STS_TILE(bkA, ctA, 0);
    if (nt > 1) LDG_TILE(bkB, ctB, 1);
    __syncthreads();

    // ---- main loop: two steps per iteration (ping-pong A/B) ----
    for (int t = 0; t < nt; t += 2) {
        // step even: MMA(t) on buf0; STS(t+1) from B; LDG(t+2) -> A
        {
            if (t + 2 < nt) LDG_TILE(bkA, ctA, t + 2);
            MMA_TILE(0);
            if (t + 1 < nt) STS_TILE(bkB, ctB, 1);
            __syncthreads();
        }
        // step odd: MMA(t+1) on buf1; STS(t+2) from A; LDG(t+3) -> B
        if (t + 1 < nt) {
            if (t + 3 < nt) LDG_TILE(bkB, ctB, t + 3);
            MMA_TILE(1);
            if (t + 2 < nt) STS_TILE(bkA, ctA, 0);
            __syncthreads();
        }
    }

    // ---- norm^2 reduce across the 4 k-quarters ----
    ((float4*)smem)[tid] = nrm;
    __syncthreads();
    if (tid < 64) {
        const float4* n = (const float4*)smem;
        float4 s0 = n[tid], s1 = n[tid + 64], s2 = n[tid + 128], s3 = n[tid + 192];
        float4 s = make_float4(s0.x + s1.x + s2.x + s3.x,
                               s0.y + s1.y + s2.y + s3.y,
                               s0.z + s1.z + s2.z + s3.z,
                               s0.w + s1.w + s2.w + s3.w);
        *(float4*)(g_pnorm + (size_t)bid * MB + tid * 4) = s;
    }

    // ---- psim write ----
    {
        float* ps = g_psim + (size_t)bid * (BQ * MB);
        const int gr = lane >> 2, c2 = (lane & 3) * 2;
        #pragma unroll
        for (int fm = 0; fm < 4; ++fm)
            #pragma unroll
            for (int fn = 0; fn < 4; ++fn) {
                const int b0 = fm * 16 + gr;
                const int n  = w * 32 + fn * 8 + c2;
                *(float2*)&ps[b0 * MB + n] =
                    make_float2(acc[fm][fn][0], acc[fm][fn][1]);
                *(float2*)&ps[(b0 + 8) * MB + n] =
                    make_float2(acc[fm][fn][2], acc[fm][fn][3]);
            }
    }
}

// =====================================================================
// Kernel 2: reduce partials -> score -> argmax -> gather style row.
// =====================================================================
__global__ __launch_bounds__(1024)
void argmax_gather_kernel(const float* __restrict__ style,
                          float* __restrict__ out) {
    const int b   = blockIdx.x;
    const int tid = threadIdx.x;
    const int m   = tid & 255;
    const int q   = tid >> 8;
    const int CPQ = NCTA / 4;            // 38

    float sim = 0.f, n2 = 0.f;
    const int c0 = q * CPQ;
    for (int c = c0; c < c0 + CPQ; ++c) {
        sim += g_psim[(size_t)c * (BQ * MB) + b * MB + m];
        n2  += g_pnorm[(size_t)c * MB + m];
    }

    __shared__ float s_sim[4][256];
    __shared__ float s_n2[4][256];
    s_sim[q][m] = sim;
    s_n2[q][m]  = n2;
    __syncthreads();

    __shared__ float s_val[256];
    __shared__ int   s_idx[256];
    if (q == 0) {
        const float st = s_sim[0][m] + s_sim[1][m] + s_sim[2][m] + s_sim[3][m];
        const float nt = s_n2[0][m]  + s_n2[1][m]  + s_n2[2][m]  + s_n2[3][m];
        const float norm = fmaxf(sqrtf(nt), 1e-12f);
        s_val[m] = st / norm;
        s_idx[m] = m;
    }
    __syncthreads();

    #pragma unroll
    for (int s = 128; s > 0; s >>= 1) {
        if (tid < s) {
            const float v1 = s_val[tid + s], v0 = s_val[tid];
            const int   i1 = s_idx[tid + s], i0 = s_idx[tid];
            if (v1 > v0 || (v1 == v0 && i1 < i0)) {
                s_val[tid] = v1;
                s_idx[tid] = i1;
            }
        }
        __syncthreads();
    }
    const int idx = s_idx[0];

    const float2* src = (const float2*)(style + (size_t)idx * SDIM);
    float2* dst = (float2*)(out + (size_t)b * SDIM);
    dst[tid] = src[tid];
}

extern "C" void kernel_launch(void* const* d_in, const int* in_sizes, int n_in,
                              void* d_out, int out_size) {
    const float* content = (const float*)d_in[0];
    const float* bank    = (const float*)d_in[1];
    const float* style   = (const float*)d_in[2];
    float* out = (float*)d_out;

    cudaFuncSetAttribute(sim_mma_kernel,
                         cudaFuncAttributeMaxDynamicSharedMemorySize, SMEM_TOTAL);

    sim_mma_kernel<<<NCTA, 256, SMEM_TOTAL>>>(content, bank);
    argmax_gather_kernel<<<BQ, 1024>>>(style, out);
}